// round 2
// baseline (speedup 1.0000x reference)
#include <cuda_runtime.h>
#include <cuda_bf16.h>
#include <math.h>

// Inputs (metadata order): Xemb [8192,128] f32, scores [8192] f32 (unused),
// h_bias scalar f32, labels [8192] i32 (unused), pos_idx [P,2] i32, neg_idx [P,2] i32.
// Output: 2 floats {pos_loss, neg_loss}.

#define NUM_BLOCKS 1184   // 148 SMs * 8
#define THREADS    256    // 8 warps/block

__device__ float2 g_partials[NUM_BLOCKS];
__device__ unsigned int g_done_count = 0;

__global__ __launch_bounds__(THREADS, 4)
void pair_loss_fused_kernel(const float* __restrict__ X,
                            const float* __restrict__ h_bias,
                            const int2* __restrict__ pos_idx,
                            const int2* __restrict__ neg_idx,
                            int P,
                            float* __restrict__ out)
{
    const int lane  = threadIdx.x & 31;
    const int warp  = threadIdx.x >> 5;
    const int gwarp = (blockIdx.x * blockDim.x + threadIdx.x) >> 5;
    const int nwarp = (gridDim.x * blockDim.x) >> 5;

    const float bias = log1pf(expf(*h_bias));  // softplus

    float pos_acc = 0.0f;
    float neg_acc = 0.0f;

    // Contiguous chunk per warp: pos_idx is sorted by first index, so
    // consecutive pairs very often share idx.x -> keep row 'a' in registers.
    const long total = 2L * P;
    const long chunk = (total + nwarp - 1) / nwarp;
    const long begin = (long)gwarp * chunk;
    const long end   = min(total, begin + chunk);

    int prev_x = -1;
    float4 a = make_float4(0.f, 0.f, 0.f, 0.f);

    for (long t = begin; t < end; t++) {
        const bool is_pos = (t < P);
        const int2 idx = is_pos ? __ldg(&pos_idx[t]) : __ldg(&neg_idx[t - P]);

        if (idx.x != prev_x) {   // warp-uniform branch
            a = __ldg(((const float4*)(X + (size_t)idx.x * 128)) + lane);
            prev_x = idx.x;
        }
        const float4 b = __ldg(((const float4*)(X + (size_t)idx.y * 128)) + lane);

        const float dx = a.x - b.x;
        const float dy = a.y - b.y;
        const float dz = a.z - b.z;
        const float dw = a.w - b.w;
        float s = dx * dx + dy * dy + dz * dz + dw * dw;

        #pragma unroll
        for (int o = 16; o > 0; o >>= 1)
            s += __shfl_xor_sync(0xFFFFFFFFu, s, o);

        if (is_pos) {
            pos_acc += s;
        } else {
            const float d = sqrtf(s);
            const float r = fmaxf(bias - d, 0.0f);
            neg_acc += r * r;
        }
    }

    // Block reduce: lane 0 of each warp -> smem -> warp 0 reduces.
    __shared__ float s_pos[THREADS / 32];
    __shared__ float s_neg[THREADS / 32];
    if (lane == 0) {
        s_pos[warp] = pos_acc;
        s_neg[warp] = neg_acc;
    }
    __syncthreads();

    __shared__ bool s_is_last;
    if (warp == 0) {
        float p = (lane < THREADS / 32) ? s_pos[lane] : 0.0f;
        float n = (lane < THREADS / 32) ? s_neg[lane] : 0.0f;
        #pragma unroll
        for (int o = 4; o > 0; o >>= 1) {
            p += __shfl_xor_sync(0xFFFFFFFFu, p, o);
            n += __shfl_xor_sync(0xFFFFFFFFu, n, o);
        }
        if (lane == 0) {
            g_partials[blockIdx.x] = make_float2(p, n);
            __threadfence();
            unsigned int prev = atomicAdd(&g_done_count, 1u);
            s_is_last = (prev == (unsigned int)(gridDim.x - 1));
        }
    }
    __syncthreads();

    // Last block performs the final deterministic reduction in double.
    if (s_is_last) {
        double ps = 0.0, ns = 0.0;
        for (int i = threadIdx.x; i < NUM_BLOCKS; i += THREADS) {
            float2 v = g_partials[i];
            ps += (double)v.x;
            ns += (double)v.y;
        }
        #pragma unroll
        for (int o = 16; o > 0; o >>= 1) {
            ps += __shfl_xor_sync(0xFFFFFFFFu, ps, o);
            ns += __shfl_xor_sync(0xFFFFFFFFu, ns, o);
        }
        __shared__ double sp[THREADS / 32], sn[THREADS / 32];
        if (lane == 0) { sp[warp] = ps; sn[warp] = ns; }
        __syncthreads();
        if (threadIdx.x == 0) {
            double tp = 0.0, tn = 0.0;
            for (int w = 0; w < THREADS / 32; w++) { tp += sp[w]; tn += sn[w]; }
            out[0] = (float)(0.5 * tp / (double)P);
            out[1] = (float)(0.5 * tn / (double)P);
            g_done_count = 0;   // reset for next graph replay
        }
    }
}

extern "C" void kernel_launch(void* const* d_in, const int* in_sizes, int n_in,
                              void* d_out, int out_size)
{
    const float* X      = (const float*)d_in[0];
    const float* h_bias = (const float*)d_in[2];
    const int2*  pos    = (const int2*)d_in[4];
    const int2*  neg    = (const int2*)d_in[5];
    const int P = in_sizes[4] / 2;

    pair_loss_fused_kernel<<<NUM_BLOCKS, THREADS>>>(X, h_bias, pos, neg, P, (float*)d_out);
}

// round 3
// speedup vs baseline: 1.8648x; 1.8648x over previous
#include <cuda_runtime.h>
#include <cuda_bf16.h>
#include <math.h>

// Inputs (metadata order): Xemb [8192,128] f32, scores f32 (unused),
// h_bias scalar f32, labels i32 (unused), pos_idx [P,2] i32, neg_idx [P,2] i32.
// Output: 2 floats {pos_loss, neg_loss}.

#define NUM_BLOCKS 592    // 148 SMs * 4 (one wave at occ=4)
#define THREADS    256    // 8 warps/block

__device__ float2 g_partials[NUM_BLOCKS];
__device__ unsigned int g_done_count = 0;

__device__ __forceinline__ float pair_partial(const float* __restrict__ X,
                                              int2 idx, int sub)
{
    const float4* ra = (const float4*)(X + (size_t)idx.x * 128);
    const float4* rb = (const float4*)(X + (size_t)idx.y * 128);
    // 8 independent LDG.128s; each group of 8 lanes covers 128B contiguous per load.
    float4 a0 = __ldg(ra + sub);       float4 a1 = __ldg(ra + sub + 8);
    float4 a2 = __ldg(ra + sub + 16);  float4 a3 = __ldg(ra + sub + 24);
    float4 b0 = __ldg(rb + sub);       float4 b1 = __ldg(rb + sub + 8);
    float4 b2 = __ldg(rb + sub + 16);  float4 b3 = __ldg(rb + sub + 24);

    float s = 0.f, d;
    d = a0.x - b0.x; s += d * d;  d = a0.y - b0.y; s += d * d;
    d = a0.z - b0.z; s += d * d;  d = a0.w - b0.w; s += d * d;
    d = a1.x - b1.x; s += d * d;  d = a1.y - b1.y; s += d * d;
    d = a1.z - b1.z; s += d * d;  d = a1.w - b1.w; s += d * d;
    d = a2.x - b2.x; s += d * d;  d = a2.y - b2.y; s += d * d;
    d = a2.z - b2.z; s += d * d;  d = a2.w - b2.w; s += d * d;
    d = a3.x - b3.x; s += d * d;  d = a3.y - b3.y; s += d * d;
    d = a3.z - b3.z; s += d * d;  d = a3.w - b3.w; s += d * d;
    return s;
}

__global__ __launch_bounds__(THREADS, 4)
void pair_loss_fused_kernel(const float* __restrict__ X,
                            const float* __restrict__ h_bias,
                            const int2* __restrict__ pos_idx,
                            const int2* __restrict__ neg_idx,
                            int P,
                            float* __restrict__ out)
{
    const int lane  = threadIdx.x & 31;
    const int warp  = threadIdx.x >> 5;
    const int grp   = lane >> 3;       // 0..3: which pair within the warp
    const int sub   = lane & 7;        // 0..7: lane within the pair group
    const int gwarp = (blockIdx.x * blockDim.x + threadIdx.x) >> 5;
    const int G     = ((NUM_BLOCKS * THREADS) >> 5) * 4;   // total groups
    const long g0   = (long)gwarp * 4;                     // warp's first group id
    const long ggrp = g0 + grp;                            // this group's id

    const float bias = log1pf(expf(*h_bias));  // softplus

    float pos_acc = 0.0f;   // per-lane partial (no per-pair reduce needed)
    float neg_acc = 0.0f;

    // ---- positive pairs ----
    {
        // warp-uniform trip count (max over groups = based on g0)
        const long nIter = (P > g0) ? ((P - 1 - g0) / G + 1) : 0;
        long t = ggrp;
        for (long k = 0; k < nIter; k++, t += G) {
            const bool valid = (t < P);
            const int2 idx = valid ? __ldg(&pos_idx[t]) : make_int2(0, 0);
            // invalid -> rows identical -> contributes exactly 0
            pos_acc += pair_partial(X, idx, sub);
        }
    }

    // ---- negative pairs ----
    {
        const long nIter = (P > g0) ? ((P - 1 - g0) / G + 1) : 0;
        long t = ggrp;
        for (long k = 0; k < nIter; k++, t += G) {
            const bool valid = (t < P);
            const int2 idx = valid ? __ldg(&neg_idx[t]) : make_int2(0, 0);
            float s = pair_partial(X, idx, sub);
            // reduce within the 8-lane group (xor offsets < 8 stay in-group)
            s += __shfl_xor_sync(0xFFFFFFFFu, s, 1);
            s += __shfl_xor_sync(0xFFFFFFFFu, s, 2);
            s += __shfl_xor_sync(0xFFFFFFFFu, s, 4);
            const float dd = sqrtf(s);
            const float r  = fmaxf(bias - dd, 0.0f);
            neg_acc += (valid && sub == 0) ? r * r : 0.0f;
        }
    }

    // ---- block reduce ----
    __shared__ float s_pos[THREADS / 32];
    __shared__ float s_neg[THREADS / 32];
    float p = pos_acc, n = neg_acc;
    #pragma unroll
    for (int o = 16; o > 0; o >>= 1) {
        p += __shfl_xor_sync(0xFFFFFFFFu, p, o);
        n += __shfl_xor_sync(0xFFFFFFFFu, n, o);
    }
    if (lane == 0) { s_pos[warp] = p; s_neg[warp] = n; }
    __syncthreads();

    __shared__ bool s_is_last;
    if (warp == 0) {
        float pp = (lane < THREADS / 32) ? s_pos[lane] : 0.0f;
        float nn = (lane < THREADS / 32) ? s_neg[lane] : 0.0f;
        #pragma unroll
        for (int o = 4; o > 0; o >>= 1) {
            pp += __shfl_xor_sync(0xFFFFFFFFu, pp, o);
            nn += __shfl_xor_sync(0xFFFFFFFFu, nn, o);
        }
        if (lane == 0) {
            g_partials[blockIdx.x] = make_float2(pp, nn);
            __threadfence();
            unsigned int prev = atomicAdd(&g_done_count, 1u);
            s_is_last = (prev == (unsigned int)(gridDim.x - 1));
        }
    }
    __syncthreads();

    // ---- last block: final deterministic reduction in double ----
    if (s_is_last) {
        double ps = 0.0, ns = 0.0;
        for (int i = threadIdx.x; i < NUM_BLOCKS; i += THREADS) {
            float2 v = g_partials[i];
            ps += (double)v.x;
            ns += (double)v.y;
        }
        #pragma unroll
        for (int o = 16; o > 0; o >>= 1) {
            ps += __shfl_xor_sync(0xFFFFFFFFu, ps, o);
            ns += __shfl_xor_sync(0xFFFFFFFFu, ns, o);
        }
        __shared__ double sp[THREADS / 32], sn[THREADS / 32];
        if (lane == 0) { sp[warp] = ps; sn[warp] = ns; }
        __syncthreads();
        if (threadIdx.x == 0) {
            double tp = 0.0, tn = 0.0;
            for (int w = 0; w < THREADS / 32; w++) { tp += sp[w]; tn += sn[w]; }
            out[0] = (float)(0.5 * tp / (double)P);
            out[1] = (float)(0.5 * tn / (double)P);
            g_done_count = 0;   // reset for next graph replay
        }
    }
}

extern "C" void kernel_launch(void* const* d_in, const int* in_sizes, int n_in,
                              void* d_out, int out_size)
{
    const float* X      = (const float*)d_in[0];
    const float* h_bias = (const float*)d_in[2];
    const int2*  pos    = (const int2*)d_in[4];
    const int2*  neg    = (const int2*)d_in[5];
    const int P = in_sizes[4] / 2;

    pair_loss_fused_kernel<<<NUM_BLOCKS, THREADS>>>(X, h_bias, pos, neg, P, (float*)d_out);
}